// round 2
// baseline (speedup 1.0000x reference)
#include <cuda_runtime.h>
#include <math.h>

#define N_NODES 97
#define IN_T    12
#define HID     6
#define NG      24           // 4*HID gates
#define MAX_T   16384
#define C1      194

// ---------------- scratch (device globals; no runtime allocation) ----------------
__device__ float g_xp [MAX_T * N_NODES * NG];   // x-projection + biases (T,97,24)
__device__ float g_al [MAX_T * N_NODES * HID];  // LSTM outputs (T,97,6)
__device__ float g_f1 [MAX_T * C1 * HID];       // conv1 out (T,194,6)
__device__ float g_f2 [MAX_T * C1 * HID];       // conv2 out (T,194,6)
__device__ float g_f3 [MAX_T * N_NODES * HID];  // conv3 out (T,97,6)
__device__ float g_wt1[97  * 3 * 194];          // [ci][kh][co]
__device__ float g_wt2[194 * 3 * 194];
__device__ float g_wt3[194 * 3 * 97];
__device__ float g_scale[N_NODES];
__device__ float g_shift[N_NODES];

// ---------------- weight transpose: OIHW (kw=1 column only) -> [ci][kh][co] ------
__global__ void prep_weights(const float* __restrict__ Wc1,
                             const float* __restrict__ Wc2,
                             const float* __restrict__ Wc3) {
    int i = blockIdx.x * blockDim.x + threadIdx.x;
    if (i < 97 * 3 * 194) {
        int co = i % 194, kh = (i / 194) % 3, ci = i / (194 * 3);
        g_wt1[i] = Wc1[((co * 97 + ci) * 3 + kh) * 3 + 1];
    }
    if (i < 194 * 3 * 194) {
        int co = i % 194, kh = (i / 194) % 3, ci = i / (194 * 3);
        g_wt2[i] = Wc2[((co * 194 + ci) * 3 + kh) * 3 + 1];
    }
    if (i < 194 * 3 * 97) {
        int co = i % 97, kh = (i / 97) % 3, ci = i / (97 * 3);
        g_wt3[i] = Wc3[((co * 194 + ci) * 3 + kh) * 3 + 1];
    }
}

// ---------------- x_proj[t,n,g] = b_ih[g]+b_hh[g] + sum_f X[t,n,f]*W_ih[g,f] -----
__global__ void xproj_kernel(const float* __restrict__ X,
                             const float* __restrict__ W_ih,
                             const float* __restrict__ b_ih,
                             const float* __restrict__ b_hh,
                             int TN) {
    __shared__ float sw[NG * IN_T];
    __shared__ float sb[NG];
    int tid = threadIdx.x;
    if (tid < NG * IN_T) sw[tid] = W_ih[tid];
    if (tid < NG)        sb[tid] = b_ih[tid] + b_hh[tid];
    __syncthreads();
    int r = blockIdx.x * blockDim.x + tid;
    if (r >= TN) return;
    const float4* xp4 = reinterpret_cast<const float4*>(X + (size_t)r * IN_T);
    float4 a = xp4[0], b = xp4[1], c = xp4[2];
    float x[IN_T] = {a.x,a.y,a.z,a.w, b.x,b.y,b.z,b.w, c.x,c.y,c.z,c.w};
    float* out = g_xp + (size_t)r * NG;
    #pragma unroll
    for (int g = 0; g < NG; g++) {
        float acc = sb[g];
        #pragma unroll
        for (int f = 0; f < IN_T; f++) acc = fmaf(sw[g * IN_T + f], x[f], acc);
        out[g] = acc;
    }
}

// ---------------- LSTM scan: one warp per node, lane = gate row ------------------
__device__ __forceinline__ float fast_sigmoid(float x) {
    return __fdividef(1.f, 1.f + __expf(-x));
}

__global__ void lstm_kernel(const float* __restrict__ W_hh, int T) {
    const int n    = blockIdx.x;
    const int lane = threadIdx.x;
    const int gl   = lane < NG ? lane : 0;
    const bool isg = (gl >= 12 && gl < 18);    // tanh gate rows
    float w[HID];
    #pragma unroll
    for (int j = 0; j < HID; j++) w[j] = W_hh[gl * HID + j];

    const float* xp  = g_xp + n * NG + gl;
    const int    STR = N_NODES * NG;
    const int    PF  = 8;
    float buf[PF];
    #pragma unroll
    for (int p = 0; p < PF; p++) buf[p] = xp[(size_t)p * STR];

    float h[HID];
    #pragma unroll
    for (int j = 0; j < HID; j++) h[j] = 0.f;
    float c = 0.f;

    float* al = g_al + n * HID + lane;   // used by lanes 0..5
    const unsigned FULL = 0xffffffffu;

    for (int t = 0; t < T; t++) {
        float gate = buf[t & (PF - 1)];
        int tp = t + PF;
        if (tp < T) buf[t & (PF - 1)] = xp[(size_t)tp * STR];   // deep prefetch

        #pragma unroll
        for (int j = 0; j < HID; j++) gate = fmaf(w[j], h[j], gate);

        // unified activation: sigmoid for i/f/o lanes, tanh (=2*sig(2x)-1) for g lanes
        float xs  = isg ? 2.f * gate : gate;
        float s   = fast_sigmoid(xs);
        float act = isg ? fmaf(2.f, s, -1.f) : s;

        float fv = __shfl_sync(FULL, act, lane + 6);
        float gv = __shfl_sync(FULL, act, lane + 12);
        float ov = __shfl_sync(FULL, act, lane + 18);

        // lanes 0..5 own cell state (others compute garbage, never read)
        c = fmaf(fv, c, act * gv);
        float tc = fmaf(2.f, fast_sigmoid(2.f * c), -1.f);   // tanh(c)
        float oz = ov * tc;
        float hn = fmaf(2.f, fast_sigmoid(2.f * oz), -1.f);  // tanh(o*tanh(c))

        if (lane < HID) al[(size_t)t * (N_NODES * HID)] = hn;

        #pragma unroll
        for (int j = 0; j < HID; j++) h[j] = __shfl_sync(FULL, hn, j);
    }
}

// ---------------- 3-tap conv over H=6 + bias + ReLU ------------------------------
template<int CIN, int COUT, int BX, int TT>
__global__ __launch_bounds__(BX * TT)
void conv_kernel(const float* __restrict__ in, const float* __restrict__ wt,
                 const float* __restrict__ bias, float* __restrict__ out, int T) {
    __shared__ float sin[TT * CIN * HID];
    int t0  = blockIdx.x * TT;
    int tid = threadIdx.y * BX + threadIdx.x;
    int vt  = min(TT, T - t0);                       // valid timesteps this block
    const float* src = in + (size_t)t0 * CIN * HID;
    for (int i = tid; i < vt * CIN * HID; i += BX * TT) sin[i] = src[i];
    __syncthreads();

    int co = threadIdx.x;
    int tl = threadIdx.y;
    if (co >= COUT || tl >= vt) return;

    float b  = bias[co];
    float y0 = b, y1 = b, y2 = b, y3 = b, y4 = b, y5 = b;
    const float* srow = &sin[tl * CIN * HID];
    #pragma unroll 2
    for (int ci = 0; ci < CIN; ci++) {
        const float2* a2 = reinterpret_cast<const float2*>(srow + ci * HID);
        float2 p = a2[0], q = a2[1], r = a2[2];
        float a0 = p.x, a1 = p.y, a2v = q.x, a3 = q.y, a4 = r.x, a5 = r.y;
        const float* wrow = wt + ci * 3 * COUT + co;
        float w0 = wrow[0], w1 = wrow[COUT], w2 = wrow[2 * COUT];
        y0 = fmaf(w1, a0,  fmaf(w2, a1,  y0));
        y1 = fmaf(w0, a0,  fmaf(w1, a1,  fmaf(w2, a2v, y1)));
        y2 = fmaf(w0, a1,  fmaf(w1, a2v, fmaf(w2, a3,  y2)));
        y3 = fmaf(w0, a2v, fmaf(w1, a3,  fmaf(w2, a4,  y3)));
        y4 = fmaf(w0, a3,  fmaf(w1, a4,  fmaf(w2, a5,  y4)));
        y5 = fmaf(w0, a4,  fmaf(w1, a5,  y5));
    }
    float* o = out + ((size_t)(t0 + tl) * COUT + co) * HID;
    o[0] = fmaxf(y0, 0.f); o[1] = fmaxf(y1, 0.f); o[2] = fmaxf(y2, 0.f);
    o[3] = fmaxf(y3, 0.f); o[4] = fmaxf(y4, 0.f); o[5] = fmaxf(y5, 0.f);
}

// ---------------- BN statistics per channel (fp64 accumulation) ------------------
__global__ void bn_stats(const float* __restrict__ gamma,
                         const float* __restrict__ beta, int T) {
    int n = blockIdx.x, tid = threadIdx.x;
    double s = 0.0, sq = 0.0;
    for (int t = tid; t < T; t += blockDim.x) {
        const float* p = g_f3 + ((size_t)t * N_NODES + n) * HID;
        #pragma unroll
        for (int h = 0; h < HID; h++) { float v = p[h]; s += v; sq += (double)v * v; }
    }
    __shared__ double ss[256], ssq[256];
    ss[tid] = s; ssq[tid] = sq; __syncthreads();
    for (int k = 128; k > 0; k >>= 1) {
        if (tid < k) { ss[tid] += ss[tid + k]; ssq[tid] += ssq[tid + k]; }
        __syncthreads();
    }
    if (tid == 0) {
        double cnt  = (double)T * HID;
        double mean = ss[0] / cnt;
        double var  = ssq[0] / cnt - mean * mean;
        float rstd  = (float)(1.0 / sqrt(var + 1e-5));
        float sc    = gamma[n] * rstd;
        g_scale[n]  = sc;
        g_shift[n]  = beta[n] - (float)mean * sc;
    }
}

// ---------------- BN apply + 6x6 linear -> output --------------------------------
__global__ void final_kernel(const float* __restrict__ Wl, const float* __restrict__ bl,
                             float* __restrict__ outp, int TN) {
    __shared__ float swl[HID * HID], sbl[HID], ssc[N_NODES], ssh[N_NODES];
    int tid = threadIdx.x;
    if (tid < HID * HID) swl[tid] = Wl[tid];
    if (tid < HID)       sbl[tid] = bl[tid];
    if (tid < N_NODES)  { ssc[tid] = g_scale[tid]; ssh[tid] = g_shift[tid]; }
    __syncthreads();
    int r = blockIdx.x * blockDim.x + tid;
    if (r >= TN) return;
    int n = r % N_NODES;
    const float* p = g_f3 + (size_t)r * HID;
    float v[HID];
    #pragma unroll
    for (int h = 0; h < HID; h++) v[h] = fmaf(p[h], ssc[n], ssh[n]);
    float* o = outp + (size_t)r * HID;
    #pragma unroll
    for (int j = 0; j < HID; j++) {
        float acc = sbl[j];
        #pragma unroll
        for (int k = 0; k < HID; k++) acc = fmaf(swl[j * HID + k], v[k], acc);
        o[j] = acc;
    }
}

// ---------------- launch --------------------------------------------------------
extern "C" void kernel_launch(void* const* d_in, const int* in_sizes, int n_in,
                              void* d_out, int out_size) {
    const float* X    = (const float*)d_in[1];
    const float* W_ih = (const float*)d_in[3];
    const float* W_hh = (const float*)d_in[4];
    const float* b_ih = (const float*)d_in[5];
    const float* b_hh = (const float*)d_in[6];
    const float* Wc1  = (const float*)d_in[7];
    const float* bc1  = (const float*)d_in[8];
    const float* Wc2  = (const float*)d_in[9];
    const float* bc2  = (const float*)d_in[10];
    const float* Wc3  = (const float*)d_in[11];
    const float* bc3  = (const float*)d_in[12];
    const float* gamma= (const float*)d_in[13];
    const float* beta = (const float*)d_in[14];
    const float* Wl   = (const float*)d_in[15];
    const float* bl   = (const float*)d_in[16];

    int T  = in_sizes[1] / (N_NODES * IN_T);
    int TN = T * N_NODES;

    float *p_al, *p_f1, *p_f2, *p_f3, *p_wt1, *p_wt2, *p_wt3;
    cudaGetSymbolAddress((void**)&p_al,  g_al);
    cudaGetSymbolAddress((void**)&p_f1,  g_f1);
    cudaGetSymbolAddress((void**)&p_f2,  g_f2);
    cudaGetSymbolAddress((void**)&p_f3,  g_f3);
    cudaGetSymbolAddress((void**)&p_wt1, g_wt1);
    cudaGetSymbolAddress((void**)&p_wt2, g_wt2);
    cudaGetSymbolAddress((void**)&p_wt3, g_wt3);

    prep_weights<<<(194 * 3 * 194 + 255) / 256, 256>>>(Wc1, Wc2, Wc3);
    xproj_kernel<<<(TN + 287) / 288, 288>>>(X, W_ih, b_ih, b_hh, TN);
    lstm_kernel<<<N_NODES, 32>>>(W_hh, T);

    conv_kernel<97, 194, 224, 4><<<(T + 3) / 4, dim3(224, 4)>>>(p_al, p_wt1, bc1, p_f1, T);
    conv_kernel<194, 194, 224, 4><<<(T + 3) / 4, dim3(224, 4)>>>(p_f1, p_wt2, bc2, p_f2, T);
    conv_kernel<194, 97, 128, 4><<<(T + 3) / 4, dim3(128, 4)>>>(p_f2, p_wt3, bc3, p_f3, T);

    bn_stats<<<N_NODES, 256>>>(gamma, beta, T);
    final_kernel<<<(TN + 255) / 256, 256>>>(Wl, bl, (float*)d_out, TN);
}

// round 3
// speedup vs baseline: 1.9951x; 1.9951x over previous
#include <cuda_runtime.h>
#include <math.h>

#define N_NODES 97
#define IN_T    12
#define HID     6
#define NG      24
#define MAX_T   16384
#define C1      194
#define FULLM   0xffffffffu

typedef unsigned long long ull;

// ---------------- scratch (device globals) ----------------
__device__ float4 g_xp4[MAX_T * N_NODES * HID];   // (t,n,unit) -> (i,f,g,o) pre-proj
__device__ float  g_al [MAX_T * N_NODES * HID];   // LSTM outputs (t,97,6)
__device__ float  g_f1 [MAX_T * C1 * HID];
__device__ float  g_f2 [MAX_T * C1 * HID];
__device__ float  g_f3 [MAX_T * N_NODES * HID];
__device__ float2 g_wp1[97  * 3 * 194];           // packed (w,w), layout [ci][kh][co]
__device__ float2 g_wp2[194 * 3 * 194];
__device__ float2 g_wp3[194 * 3 * 97];
__device__ float  g_scale[N_NODES];
__device__ float  g_shift[N_NODES];

// ---------------- fast activations -----------------------------------------------
__device__ __forceinline__ float tanha(float x) {
    float y; asm("tanh.approx.f32 %0, %1;" : "=f"(y) : "f"(x)); return y;
}
__device__ __forceinline__ float sigt(float x) {      // sigmoid via MUFU.TANH
    return fmaf(tanha(x * 0.5f), 0.5f, 0.5f);
}

// ---------------- packed f32x2 helpers --------------------------------------------
__device__ __forceinline__ ull pk(float lo, float hi) {
    ull r; asm("mov.b64 %0, {%1, %2};" : "=l"(r) : "f"(lo), "f"(hi)); return r;
}
__device__ __forceinline__ float2 unpk(ull v) {
    float2 f; asm("mov.b64 {%0, %1}, %2;" : "=f"(f.x), "=f"(f.y) : "l"(v)); return f;
}
__device__ __forceinline__ void fma2(ull& d, ull a, ull b) {
    asm("fma.rn.f32x2 %0, %1, %2, %0;" : "+l"(d) : "l"(a), "l"(b));
}

// ---------------- weight prep: OIHW (kw=1 col) -> packed [ci][kh][co] (w,w) -------
__global__ void prep_weights(const float* __restrict__ Wc1,
                             const float* __restrict__ Wc2,
                             const float* __restrict__ Wc3) {
    int i = blockIdx.x * blockDim.x + threadIdx.x;
    if (i < 97 * 3 * 194) {
        int co = i % 194, kh = (i / 194) % 3, ci = i / 582;
        float v = Wc1[((co * 97 + ci) * 3 + kh) * 3 + 1];
        g_wp1[i] = make_float2(v, v);
    }
    if (i < 194 * 3 * 194) {
        int co = i % 194, kh = (i / 194) % 3, ci = i / 582;
        float v = Wc2[((co * 194 + ci) * 3 + kh) * 3 + 1];
        g_wp2[i] = make_float2(v, v);
    }
    if (i < 194 * 3 * 97) {
        int co = i % 97, kh = (i / 97) % 3, ci = i / 291;
        float v = Wc3[((co * 194 + ci) * 3 + kh) * 3 + 1];
        g_wp3[i] = make_float2(v, v);
    }
}

// ---------------- x-projection: out (t,n,unit) float4 = (i,f,g,o) -----------------
__global__ void xproj_kernel(const float* __restrict__ X,
                             const float* __restrict__ W_ih,
                             const float* __restrict__ b_ih,
                             const float* __restrict__ b_hh,
                             int TN) {
    __shared__ float sw[NG * IN_T];
    __shared__ float sb[NG];
    int tid = threadIdx.x;
    if (tid < NG * IN_T) sw[tid] = W_ih[tid];
    if (tid < NG)        sb[tid] = b_ih[tid] + b_hh[tid];
    __syncthreads();
    int r = blockIdx.x * blockDim.x + tid;
    if (r >= TN) return;
    const float4* xp4 = reinterpret_cast<const float4*>(X + (size_t)r * IN_T);
    float4 a = xp4[0], b = xp4[1], c = xp4[2];
    float x[IN_T] = {a.x,a.y,a.z,a.w, b.x,b.y,b.z,b.w, c.x,c.y,c.z,c.w};
    float acc[NG];
    #pragma unroll
    for (int g = 0; g < NG; g++) {
        float s = sb[g];
        #pragma unroll
        for (int f = 0; f < IN_T; f++) s = fmaf(sw[g * IN_T + f], x[f], s);
        acc[g] = s;
    }
    float4* out = g_xp4 + (size_t)r * HID;
    #pragma unroll
    for (int j = 0; j < HID; j++)
        out[j] = make_float4(acc[j], acc[6 + j], acc[12 + j], acc[18 + j]);
}

// ---------------- LSTM scan: lane = hidden unit, 5 nodes per warp -----------------
__global__ void lstm_kernel(const float* __restrict__ W_hh, int T) {
    const int lane = threadIdx.x;
    int grp = lane / 6;
    int j   = lane - grp * 6;
    bool valid = grp < 5;
    int node = blockIdx.x * 5 + (valid ? grp : 0);
    if (node >= N_NODES) { node = 0; valid = false; }

    float wi[HID], wf[HID], wg[HID], wo[HID];
    #pragma unroll
    for (int k = 0; k < HID; k++) {
        wi[k] = W_hh[(j)      * HID + k];
        wf[k] = W_hh[(6 + j)  * HID + k];
        wg[k] = W_hh[(12 + j) * HID + k];
        wo[k] = W_hh[(18 + j) * HID + k];
    }

    const float4* xp = g_xp4 + (size_t)node * HID + j;
    const int STR = N_NODES * HID;          // 582
    const int PF = 8;
    float4 buf[PF];
    #pragma unroll
    for (int p = 0; p < PF; p++)
        buf[p] = (p < T) ? xp[(size_t)p * STR] : make_float4(0.f, 0.f, 0.f, 0.f);

    float h0 = 0.f, h1 = 0.f, h2 = 0.f, h3 = 0.f, h4 = 0.f, h5 = 0.f, c = 0.f;
    float* al = g_al + (size_t)node * HID + j;
    const int base = grp * 6;

    for (int t = 0; t < T; t += PF) {
        #pragma unroll
        for (int u = 0; u < PF; u++) {
            float4 xv = buf[u];
            int tp = t + u + PF;
            if (tp < T) buf[u] = xp[(size_t)tp * STR];

            // split dot products (depth 3 FFMA + 1 ADD after h arrives)
            float a0 = fmaf(wi[0], h0, fmaf(wi[1], h1, fmaf(wi[2], h2, xv.x)));
            float a1 = fmaf(wi[3], h3, fmaf(wi[4], h4, wi[5] * h5));
            float b0 = fmaf(wf[0], h0, fmaf(wf[1], h1, fmaf(wf[2], h2, xv.y)));
            float b1 = fmaf(wf[3], h3, fmaf(wf[4], h4, wf[5] * h5));
            float g0 = fmaf(wg[0], h0, fmaf(wg[1], h1, fmaf(wg[2], h2, xv.z)));
            float g1 = fmaf(wg[3], h3, fmaf(wg[4], h4, wg[5] * h5));
            float o0 = fmaf(wo[0], h0, fmaf(wo[1], h1, fmaf(wo[2], h2, xv.w)));
            float o1 = fmaf(wo[3], h3, fmaf(wo[4], h4, wo[5] * h5));

            float iv = sigt(a0 + a1);
            float fv = sigt(b0 + b1);
            float gv = tanha(g0 + g1);
            float ov = sigt(o0 + o1);

            c = fmaf(fv, c, iv * gv);
            float hn = tanha(ov * tanha(c));

            if (valid && (t + u) < T) al[(size_t)(t + u) * STR] = hn;

            h0 = __shfl_sync(FULLM, hn, base);
            h1 = __shfl_sync(FULLM, hn, base + 1);
            h2 = __shfl_sync(FULLM, hn, base + 2);
            h3 = __shfl_sync(FULLM, hn, base + 3);
            h4 = __shfl_sync(FULLM, hn, base + 4);
            h5 = __shfl_sync(FULLM, hn, base + 5);
        }
    }
}

// ---------------- 3-tap conv (FFMA2), bias + ReLU ---------------------------------
// sA: standard (TT,CIN,6); sB: zero-padded (TT,CIN,8) rows [0,a0..a5,0] so every
// tap pair is an aligned 8-byte LDS.
template<int CIN, int COUT>
__global__ __launch_bounds__(COUT * 2)
void conv_kernel(const float* __restrict__ in, const float2* __restrict__ wpf,
                 const float* __restrict__ bias, float* __restrict__ out, int T) {
    constexpr int TT = 4;
    __shared__ float sA[TT * CIN * 6];
    __shared__ float sB[TT * CIN * 8];
    const int nth = COUT * 2;
    int t0  = blockIdx.x * TT;
    int tid = threadIdx.y * COUT + threadIdx.x;
    int vt  = min(TT, T - t0);
    const float* src = in + (size_t)t0 * CIN * 6;
    for (int i = tid; i < vt * CIN * 6; i += nth) sA[i] = src[i];
    for (int i = tid; i < TT * CIN * 8; i += nth) {
        int tl  = i / (CIN * 8);
        int rem = i - tl * (CIN * 8);
        int ci  = rem >> 3, k = rem & 7;
        sB[i] = (k == 0 || k == 7 || tl >= vt) ? 0.f : src[(tl * CIN + ci) * 6 + k - 1];
    }
    __syncthreads();

    const int co = threadIdx.x;
    const int ty = threadIdx.y;              // 0..1 -> tslots {2*ty, 2*ty+1}
    const int ts0 = ty * 2;

    float b = bias[co];
    ull a00, a01, a02, a10, a11, a12;
    a00 = a01 = a02 = a10 = a11 = a12 = pk(b, b);

    const ull* pa0 = reinterpret_cast<const ull*>(sA + ts0 * CIN * 6);
    const ull* pa1 = reinterpret_cast<const ull*>(sA + (ts0 + 1) * CIN * 6);
    const ull* pb0 = reinterpret_cast<const ull*>(sB + ts0 * CIN * 8);
    const ull* pb1 = reinterpret_cast<const ull*>(sB + (ts0 + 1) * CIN * 8);
    const ull* wu  = reinterpret_cast<const ull*>(wpf) + co;

    #pragma unroll 2
    for (int ci = 0; ci < CIN; ci++) {
        ull W0 = wu[0], W1 = wu[COUT], W2 = wu[2 * COUT];
        wu += 3 * COUT;
        // timestep ts0
        {
            ull PA0 = pa0[ci*3+0], PA1 = pa0[ci*3+1], PA2 = pa0[ci*3+2];
            ull PB0 = pb0[ci*4+0], PB1 = pb0[ci*4+1], PB2 = pb0[ci*4+2], PB3 = pb0[ci*4+3];
            fma2(a00, W0, PB0); fma2(a00, W1, PA0); fma2(a00, W2, PB1);
            fma2(a01, W0, PB1); fma2(a01, W1, PA1); fma2(a01, W2, PB2);
            fma2(a02, W0, PB2); fma2(a02, W1, PA2); fma2(a02, W2, PB3);
        }
        // timestep ts0+1
        {
            ull PA0 = pa1[ci*3+0], PA1 = pa1[ci*3+1], PA2 = pa1[ci*3+2];
            ull PB0 = pb1[ci*4+0], PB1 = pb1[ci*4+1], PB2 = pb1[ci*4+2], PB3 = pb1[ci*4+3];
            fma2(a10, W0, PB0); fma2(a10, W1, PA0); fma2(a10, W2, PB1);
            fma2(a11, W0, PB1); fma2(a11, W1, PA1); fma2(a11, W2, PB2);
            fma2(a12, W0, PB2); fma2(a12, W1, PA2); fma2(a12, W2, PB3);
        }
    }

    if (ts0 < vt) {
        float2* o = reinterpret_cast<float2*>(out + ((size_t)(t0 + ts0) * COUT + co) * 6);
        float2 r0 = unpk(a00), r1 = unpk(a01), r2 = unpk(a02);
        o[0] = make_float2(fmaxf(r0.x, 0.f), fmaxf(r0.y, 0.f));
        o[1] = make_float2(fmaxf(r1.x, 0.f), fmaxf(r1.y, 0.f));
        o[2] = make_float2(fmaxf(r2.x, 0.f), fmaxf(r2.y, 0.f));
    }
    if (ts0 + 1 < vt) {
        float2* o = reinterpret_cast<float2*>(out + ((size_t)(t0 + ts0 + 1) * COUT + co) * 6);
        float2 r0 = unpk(a10), r1 = unpk(a11), r2 = unpk(a12);
        o[0] = make_float2(fmaxf(r0.x, 0.f), fmaxf(r0.y, 0.f));
        o[1] = make_float2(fmaxf(r1.x, 0.f), fmaxf(r1.y, 0.f));
        o[2] = make_float2(fmaxf(r2.x, 0.f), fmaxf(r2.y, 0.f));
    }
}

// ---------------- BN statistics (fp64) --------------------------------------------
__global__ void bn_stats(const float* __restrict__ gamma,
                         const float* __restrict__ beta, int T) {
    int n = blockIdx.x, tid = threadIdx.x;
    double s = 0.0, sq = 0.0;
    for (int t = tid; t < T; t += blockDim.x) {
        const float* p = g_f3 + ((size_t)t * N_NODES + n) * HID;
        #pragma unroll
        for (int h = 0; h < HID; h++) { float v = p[h]; s += v; sq += (double)v * v; }
    }
    __shared__ double ss[256], ssq[256];
    ss[tid] = s; ssq[tid] = sq; __syncthreads();
    for (int k = 128; k > 0; k >>= 1) {
        if (tid < k) { ss[tid] += ss[tid + k]; ssq[tid] += ssq[tid + k]; }
        __syncthreads();
    }
    if (tid == 0) {
        double cnt  = (double)T * HID;
        double mean = ss[0] / cnt;
        double var  = ssq[0] / cnt - mean * mean;
        float rstd  = (float)(1.0 / sqrt(var + 1e-5));
        float sc    = gamma[n] * rstd;
        g_scale[n]  = sc;
        g_shift[n]  = beta[n] - (float)mean * sc;
    }
}

// ---------------- BN apply + 6x6 linear -------------------------------------------
__global__ void final_kernel(const float* __restrict__ Wl, const float* __restrict__ bl,
                             float* __restrict__ outp, int TN) {
    __shared__ float swl[HID * HID], sbl[HID], ssc[N_NODES], ssh[N_NODES];
    int tid = threadIdx.x;
    if (tid < HID * HID) swl[tid] = Wl[tid];
    if (tid < HID)       sbl[tid] = bl[tid];
    if (tid < N_NODES)  { ssc[tid] = g_scale[tid]; ssh[tid] = g_shift[tid]; }
    __syncthreads();
    int r = blockIdx.x * blockDim.x + tid;
    if (r >= TN) return;
    int n = r % N_NODES;
    const float* p = g_f3 + (size_t)r * HID;
    float v[HID];
    #pragma unroll
    for (int h = 0; h < HID; h++) v[h] = fmaf(p[h], ssc[n], ssh[n]);
    float* o = outp + (size_t)r * HID;
    #pragma unroll
    for (int j = 0; j < HID; j++) {
        float acc = sbl[j];
        #pragma unroll
        for (int k = 0; k < HID; k++) acc = fmaf(swl[j * HID + k], v[k], acc);
        o[j] = acc;
    }
}

// ---------------- launch ----------------------------------------------------------
extern "C" void kernel_launch(void* const* d_in, const int* in_sizes, int n_in,
                              void* d_out, int out_size) {
    const float* X    = (const float*)d_in[1];
    const float* W_ih = (const float*)d_in[3];
    const float* W_hh = (const float*)d_in[4];
    const float* b_ih = (const float*)d_in[5];
    const float* b_hh = (const float*)d_in[6];
    const float* Wc1  = (const float*)d_in[7];
    const float* bc1  = (const float*)d_in[8];
    const float* Wc2  = (const float*)d_in[9];
    const float* bc2  = (const float*)d_in[10];
    const float* Wc3  = (const float*)d_in[11];
    const float* bc3  = (const float*)d_in[12];
    const float* gamma= (const float*)d_in[13];
    const float* beta = (const float*)d_in[14];
    const float* Wl   = (const float*)d_in[15];
    const float* bl   = (const float*)d_in[16];

    int T  = in_sizes[1] / (N_NODES * IN_T);
    int TN = T * N_NODES;

    float  *p_al, *p_f1, *p_f2, *p_f3;
    float2 *p_w1, *p_w2, *p_w3;
    cudaGetSymbolAddress((void**)&p_al, g_al);
    cudaGetSymbolAddress((void**)&p_f1, g_f1);
    cudaGetSymbolAddress((void**)&p_f2, g_f2);
    cudaGetSymbolAddress((void**)&p_f3, g_f3);
    cudaGetSymbolAddress((void**)&p_w1, g_wp1);
    cudaGetSymbolAddress((void**)&p_w2, g_wp2);
    cudaGetSymbolAddress((void**)&p_w3, g_wp3);

    prep_weights<<<(194 * 3 * 194 + 255) / 256, 256>>>(Wc1, Wc2, Wc3);
    xproj_kernel<<<(TN + 287) / 288, 288>>>(X, W_ih, b_ih, b_hh, TN);
    lstm_kernel<<<(N_NODES + 4) / 5, 32>>>(W_hh, T);

    conv_kernel<97, 194><<<(T + 3) / 4, dim3(194, 2)>>>(p_al, p_w1, bc1, p_f1, T);
    conv_kernel<194, 194><<<(T + 3) / 4, dim3(194, 2)>>>(p_f1, p_w2, bc2, p_f2, T);
    conv_kernel<194, 97><<<(T + 3) / 4, dim3(97, 2)>>>(p_f2, p_w3, bc3, p_f3, T);

    bn_stats<<<N_NODES, 256>>>(gamma, beta, T);
    final_kernel<<<(TN + 255) / 256, 256>>>(Wl, bl, (float*)d_out, TN);
}

// round 5
// speedup vs baseline: 3.1915x; 1.5996x over previous
#include <cuda_runtime.h>
#include <math.h>

#define N_NODES 97
#define IN_T    12
#define HID     6
#define NG      24
#define MAX_T   16384
#define C1      194
#define FULLM   0xffffffffu
#define CHUNK   64
#define NCHUNK  (MAX_T / CHUNK)
#define NPROD   20                 // ceil(97/5) LSTM producer blocks
#define NBLK    148
#define NTHR    388                // 194 x 2

// ---------------- scratch (device globals) ----------------
__device__ float4 g_xp4[MAX_T * N_NODES * HID];   // (t,n,unit) -> (i,f,g,o)
__device__ float  g_al [MAX_T * N_NODES * HID];   // LSTM outputs (t,97,6)
__device__ float  g_f3 [MAX_T * N_NODES * HID];   // conv3 out (t,97,6)
__device__ float  g_wt1[97  * 3 * 194];           // [ci][kh][co]
__device__ float  g_wt2[194 * 3 * 194];
__device__ float  g_wt3[194 * 3 * 97];
__device__ float  g_scale[N_NODES];
__device__ float  g_shift[N_NODES];
__device__ int    g_done[NCHUNK];

// ---------------- fast activations ------------------------------------------------
__device__ __forceinline__ float tanha(float x) {
    float y; asm("tanh.approx.f32 %0, %1;" : "=f"(y) : "f"(x)); return y;
}
__device__ __forceinline__ float sigt(float x) {
    return fmaf(tanha(x * 0.5f), 0.5f, 0.5f);
}

// ---------------- weight prep: OIHW (kw=1 col) -> [ci][kh][co] --------------------
__global__ void prep_weights(const float* __restrict__ Wc1,
                             const float* __restrict__ Wc2,
                             const float* __restrict__ Wc3) {
    int i = blockIdx.x * blockDim.x + threadIdx.x;
    if (i < 97 * 3 * 194) {
        int co = i % 194, kh = (i / 194) % 3, ci = i / 582;
        g_wt1[i] = Wc1[((co * 97 + ci) * 3 + kh) * 3 + 1];
    }
    if (i < 194 * 3 * 194) {
        int co = i % 194, kh = (i / 194) % 3, ci = i / 582;
        g_wt2[i] = Wc2[((co * 194 + ci) * 3 + kh) * 3 + 1];
    }
    if (i < 194 * 3 * 97) {
        int co = i % 97, kh = (i / 97) % 3, ci = i / 291;
        g_wt3[i] = Wc3[((co * 194 + ci) * 3 + kh) * 3 + 1];
    }
}

__global__ void reset_done() {
    int i = threadIdx.x;
    if (i < NCHUNK) g_done[i] = 0;
}

// ---------------- x-projection: (t,n,unit) float4 = (i,f,g,o) ---------------------
__global__ void xproj_kernel(const float* __restrict__ X,
                             const float* __restrict__ W_ih,
                             const float* __restrict__ b_ih,
                             const float* __restrict__ b_hh,
                             int TN) {
    __shared__ float sw[NG * IN_T];
    __shared__ float sb[NG];
    int tid = threadIdx.x;
    if (tid < NG * IN_T) sw[tid] = W_ih[tid];
    if (tid < NG)        sb[tid] = b_ih[tid] + b_hh[tid];
    __syncthreads();
    int r = blockIdx.x * blockDim.x + tid;
    if (r >= TN) return;
    const float4* xp4 = reinterpret_cast<const float4*>(X + (size_t)r * IN_T);
    float4 a = xp4[0], b = xp4[1], c = xp4[2];
    float x[IN_T] = {a.x,a.y,a.z,a.w, b.x,b.y,b.z,b.w, c.x,c.y,c.z,c.w};
    float acc[NG];
    #pragma unroll
    for (int g = 0; g < NG; g++) {
        float s = sb[g];
        #pragma unroll
        for (int f = 0; f < IN_T; f++) s = fmaf(sw[g * IN_T + f], x[f], s);
        acc[g] = s;
    }
    float4* out = g_xp4 + (size_t)r * HID;
    #pragma unroll
    for (int j = 0; j < HID; j++)
        out[j] = make_float4(acc[j], acc[6 + j], acc[12 + j], acc[18 + j]);
}

// ---------------- fused conv pair: 2 timesteps per thread -------------------------
template<int CIN>
__device__ __forceinline__ void conv_pair(const float* __restrict__ sin0,
                                          const float* __restrict__ sin1,
                                          const float* __restrict__ wt,
                                          int cout, int co, float bias,
                                          float* y0, float* y1) {
    #pragma unroll
    for (int k = 0; k < 6; k++) { y0[k] = bias; y1[k] = bias; }
    const float* w = wt + co;
    #pragma unroll 2
    for (int ci = 0; ci < CIN; ci++) {
        float w0 = w[0], w1 = w[cout], w2 = w[2 * cout];
        w += 3 * cout;
        {
            const float2* A = reinterpret_cast<const float2*>(sin0 + ci * 6);
            float2 p = A[0], q = A[1], r = A[2];
            y0[0] = fmaf(w1, p.x, fmaf(w2, p.y, y0[0]));
            y0[1] = fmaf(w0, p.x, fmaf(w1, p.y, fmaf(w2, q.x, y0[1])));
            y0[2] = fmaf(w0, p.y, fmaf(w1, q.x, fmaf(w2, q.y, y0[2])));
            y0[3] = fmaf(w0, q.x, fmaf(w1, q.y, fmaf(w2, r.x, y0[3])));
            y0[4] = fmaf(w0, q.y, fmaf(w1, r.x, fmaf(w2, r.y, y0[4])));
            y0[5] = fmaf(w0, r.x, fmaf(w1, r.y, y0[5]));
        }
        {
            const float2* B = reinterpret_cast<const float2*>(sin1 + ci * 6);
            float2 p = B[0], q = B[1], r = B[2];
            y1[0] = fmaf(w1, p.x, fmaf(w2, p.y, y1[0]));
            y1[1] = fmaf(w0, p.x, fmaf(w1, p.y, fmaf(w2, q.x, y1[1])));
            y1[2] = fmaf(w0, p.y, fmaf(w1, q.x, fmaf(w2, q.y, y1[2])));
            y1[3] = fmaf(w0, q.x, fmaf(w1, q.y, fmaf(w2, r.x, y1[3])));
            y1[4] = fmaf(w0, q.y, fmaf(w1, r.x, fmaf(w2, r.y, y1[4])));
            y1[5] = fmaf(w0, r.x, fmaf(w1, r.y, y1[5]));
        }
    }
    #pragma unroll
    for (int k = 0; k < 6; k++) { y0[k] = fmaxf(y0[k], 0.f); y1[k] = fmaxf(y1[k], 0.f); }
}

// ---------------- persistent mega kernel: LSTM producers + fused conv consumers ---
__global__ __launch_bounds__(NTHR, 1)
void mega_kernel(const float* __restrict__ W_hh,
                 const float* __restrict__ bc1,
                 const float* __restrict__ bc2,
                 const float* __restrict__ bc3,
                 int T) {
    __shared__ float s_in[4 * 582];     //  9312 B
    __shared__ float s_f1[4 * 1164];    // 18624 B
    __shared__ float s_f2[4 * 1164];    // 18624 B  (total 45.4 KB)

    const int tid = threadIdx.y * 194 + threadIdx.x;

    if (blockIdx.x < NPROD) {
        // ===================== LSTM producer (warp 0 only) =======================
        if (tid >= 32) return;
        const int lane = tid;
        int grp = lane / 6;
        int j   = lane - grp * 6;
        bool valid = grp < 5;
        int node = blockIdx.x * 5 + (valid ? grp : 0);
        if (node >= N_NODES) { node = 0; valid = false; }

        float wi[HID], wf[HID], wg[HID], wo[HID];
        #pragma unroll
        for (int k = 0; k < HID; k++) {
            wi[k] = W_hh[(j)      * HID + k];
            wf[k] = W_hh[(6 + j)  * HID + k];
            wg[k] = W_hh[(12 + j) * HID + k];
            wo[k] = W_hh[(18 + j) * HID + k];
        }

        const float4* xp = g_xp4 + (size_t)node * HID + j;
        const int STR = N_NODES * HID;        // 582
        const int PF = 8;
        float4 buf[PF];
        #pragma unroll
        for (int p = 0; p < PF; p++)
            buf[p] = (p < T) ? xp[(size_t)p * STR] : make_float4(0.f, 0.f, 0.f, 0.f);

        float h0 = 0.f, h1 = 0.f, h2 = 0.f, h3 = 0.f, h4 = 0.f, h5 = 0.f, c = 0.f;
        float* al = g_al + (size_t)node * HID + j;
        const int base = grp * 6;

        for (int t = 0; t < T; t += PF) {
            #pragma unroll
            for (int u = 0; u < PF; u++) {
                float4 xv = buf[u];
                int tp = t + u + PF;
                if (tp < T) buf[u] = xp[(size_t)tp * STR];

                float a0 = fmaf(wi[0], h0, fmaf(wi[1], h1, fmaf(wi[2], h2, xv.x)));
                float a1 = fmaf(wi[3], h3, fmaf(wi[4], h4, wi[5] * h5));
                float b0 = fmaf(wf[0], h0, fmaf(wf[1], h1, fmaf(wf[2], h2, xv.y)));
                float b1 = fmaf(wf[3], h3, fmaf(wf[4], h4, wf[5] * h5));
                float g0 = fmaf(wg[0], h0, fmaf(wg[1], h1, fmaf(wg[2], h2, xv.z)));
                float g1 = fmaf(wg[3], h3, fmaf(wg[4], h4, wg[5] * h5));
                float o0 = fmaf(wo[0], h0, fmaf(wo[1], h1, fmaf(wo[2], h2, xv.w)));
                float o1 = fmaf(wo[3], h3, fmaf(wo[4], h4, wo[5] * h5));

                float iv = sigt(a0 + a1);
                float fv = sigt(b0 + b1);
                float gv = tanha(g0 + g1);
                float ov = sigt(o0 + o1);          // verified round-3 form

                c = fmaf(fv, c, iv * gv);
                float tc = tanha(c);
                float hn = tanha(ov * tc);

                if (valid && (t + u) < T) al[(size_t)(t + u) * STR] = hn;

                h0 = __shfl_sync(FULLM, hn, base);
                h1 = __shfl_sync(FULLM, hn, base + 1);
                h2 = __shfl_sync(FULLM, hn, base + 2);
                h3 = __shfl_sync(FULLM, hn, base + 3);
                h4 = __shfl_sync(FULLM, hn, base + 4);
                h5 = __shfl_sync(FULLM, hn, base + 5);
            }
            if (((t + PF) & (CHUNK - 1)) == 0) {
                __threadfence();
                if (lane == 0) atomicAdd(&g_done[((t + PF) >> 6) - 1], 1);
            }
        }
        if (T & (CHUNK - 1)) {          // tail chunk (not hit for T=16384)
            __threadfence();
            if (lane == 0) atomicAdd(&g_done[T >> 6], 1);
        }
        return;
    }

    // ===================== fused conv consumer ==================================
    const int cb = blockIdx.x - NPROD;       // 0..127
    const int co = threadIdx.x;              // 0..193
    const int y  = threadIdx.y;              // 0..1 -> timesteps {y, y+2}

    const float b1 = __ldg(bc1 + co);
    const float b2 = __ldg(bc2 + co);
    const float b3 = (co < 97) ? __ldg(bc3 + co) : 0.f;

    float r0[6], r1[6];

    for (int p = cb; p * 4 < T; p += (NBLK - NPROD)) {
        int t0 = p * 4;
        int last = min(t0 + 3, T - 1);
        int need = last >> 6;                // chunk index that must be complete

        if (tid == 0) {
            volatile int* dp = g_done + need;
            while (*dp < NPROD) __nanosleep(128);
        }
        __syncthreads();

        // load al[t0..t0+3] (2328 floats = 582 float4), L2-only to dodge stale L1
        {
            const float4* src = reinterpret_cast<const float4*>(g_al + (size_t)t0 * 582);
            float4* dst = reinterpret_cast<float4*>(s_in);
            for (int i = tid; i < 582; i += NTHR) dst[i] = __ldcg(src + i);
        }
        __syncthreads();

        // conv1: 97 -> 194
        conv_pair<97>(s_in + y * 582, s_in + (y + 2) * 582, g_wt1, 194, co, b1, r0, r1);
        {
            float2* o0 = reinterpret_cast<float2*>(s_f1 + y * 1164 + co * 6);
            float2* o1 = reinterpret_cast<float2*>(s_f1 + (y + 2) * 1164 + co * 6);
            o0[0] = make_float2(r0[0], r0[1]); o0[1] = make_float2(r0[2], r0[3]); o0[2] = make_float2(r0[4], r0[5]);
            o1[0] = make_float2(r1[0], r1[1]); o1[1] = make_float2(r1[2], r1[3]); o1[2] = make_float2(r1[4], r1[5]);
        }
        __syncthreads();

        // conv2: 194 -> 194
        conv_pair<194>(s_f1 + y * 1164, s_f1 + (y + 2) * 1164, g_wt2, 194, co, b2, r0, r1);
        {
            float2* o0 = reinterpret_cast<float2*>(s_f2 + y * 1164 + co * 6);
            float2* o1 = reinterpret_cast<float2*>(s_f2 + (y + 2) * 1164 + co * 6);
            o0[0] = make_float2(r0[0], r0[1]); o0[1] = make_float2(r0[2], r0[3]); o0[2] = make_float2(r0[4], r0[5]);
            o1[0] = make_float2(r1[0], r1[1]); o1[1] = make_float2(r1[2], r1[3]); o1[2] = make_float2(r1[4], r1[5]);
        }
        __syncthreads();

        // conv3: 194 -> 97 (threads co>=97 idle)
        if (co < 97) {
            conv_pair<194>(s_f2 + y * 1164, s_f2 + (y + 2) * 1164, g_wt3, 97, co, b3, r0, r1);
            float2* o0 = reinterpret_cast<float2*>(g_f3 + (size_t)(t0 + y) * 582 + co * 6);
            float2* o1 = reinterpret_cast<float2*>(g_f3 + (size_t)(t0 + y + 2) * 582 + co * 6);
            o0[0] = make_float2(r0[0], r0[1]); o0[1] = make_float2(r0[2], r0[3]); o0[2] = make_float2(r0[4], r0[5]);
            o1[0] = make_float2(r1[0], r1[1]); o1[1] = make_float2(r1[2], r1[3]); o1[2] = make_float2(r1[4], r1[5]);
        }
        __syncthreads();
    }
}

// ---------------- BN statistics (fp64) --------------------------------------------
__global__ void bn_stats(const float* __restrict__ gamma,
                         const float* __restrict__ beta, int T) {
    int n = blockIdx.x, tid = threadIdx.x;
    double s = 0.0, sq = 0.0;
    for (int t = tid; t < T; t += blockDim.x) {
        const float* p = g_f3 + ((size_t)t * N_NODES + n) * HID;
        #pragma unroll
        for (int h = 0; h < HID; h++) { float v = p[h]; s += v; sq += (double)v * v; }
    }
    __shared__ double ss[256], ssq[256];
    ss[tid] = s; ssq[tid] = sq; __syncthreads();
    for (int k = 128; k > 0; k >>= 1) {
        if (tid < k) { ss[tid] += ss[tid + k]; ssq[tid] += ssq[tid + k]; }
        __syncthreads();
    }
    if (tid == 0) {
        double cnt  = (double)T * HID;
        double mean = ss[0] / cnt;
        double var  = ssq[0] / cnt - mean * mean;
        float rstd  = (float)(1.0 / sqrt(var + 1e-5));
        float sc    = gamma[n] * rstd;
        g_scale[n]  = sc;
        g_shift[n]  = beta[n] - (float)mean * sc;
    }
}

// ---------------- BN apply + 6x6 linear -------------------------------------------
__global__ void final_kernel(const float* __restrict__ Wl, const float* __restrict__ bl,
                             float* __restrict__ outp, int TN) {
    __shared__ float swl[HID * HID], sbl[HID], ssc[N_NODES], ssh[N_NODES];
    int tid = threadIdx.x;
    if (tid < HID * HID) swl[tid] = Wl[tid];
    if (tid < HID)       sbl[tid] = bl[tid];
    if (tid < N_NODES)  { ssc[tid] = g_scale[tid]; ssh[tid] = g_shift[tid]; }
    __syncthreads();
    int r = blockIdx.x * blockDim.x + tid;
    if (r >= TN) return;
    int n = r % N_NODES;
    const float* p = g_f3 + (size_t)r * HID;
    float v[HID];
    #pragma unroll
    for (int h = 0; h < HID; h++) v[h] = fmaf(p[h], ssc[n], ssh[n]);
    float* o = outp + (size_t)r * HID;
    #pragma unroll
    for (int j = 0; j < HID; j++) {
        float acc = sbl[j];
        #pragma unroll
        for (int k = 0; k < HID; k++) acc = fmaf(swl[j * HID + k], v[k], acc);
        o[j] = acc;
    }
}

// ---------------- launch ----------------------------------------------------------
extern "C" void kernel_launch(void* const* d_in, const int* in_sizes, int n_in,
                              void* d_out, int out_size) {
    const float* X    = (const float*)d_in[1];
    const float* W_ih = (const float*)d_in[3];
    const float* W_hh = (const float*)d_in[4];
    const float* b_ih = (const float*)d_in[5];
    const float* b_hh = (const float*)d_in[6];
    const float* Wc1  = (const float*)d_in[7];
    const float* bc1  = (const float*)d_in[8];
    const float* Wc2  = (const float*)d_in[9];
    const float* bc2  = (const float*)d_in[10];
    const float* Wc3  = (const float*)d_in[11];
    const float* bc3  = (const float*)d_in[12];
    const float* gamma= (const float*)d_in[13];
    const float* beta = (const float*)d_in[14];
    const float* Wl   = (const float*)d_in[15];
    const float* bl   = (const float*)d_in[16];

    int T  = in_sizes[1] / (N_NODES * IN_T);
    int TN = T * N_NODES;

    prep_weights<<<(194 * 3 * 194 + 255) / 256, 256>>>(Wc1, Wc2, Wc3);
    reset_done<<<1, 256>>>();
    xproj_kernel<<<(TN + 287) / 288, 288>>>(X, W_ih, b_ih, b_hh, TN);

    mega_kernel<<<NBLK, dim3(194, 2)>>>(W_hh, bc1, bc2, bc3, T);

    bn_stats<<<N_NODES, 256>>>(gamma, beta, T);
    final_kernel<<<(TN + 255) / 256, 256>>>(Wl, bl, (float*)d_out, TN);
}